// round 17
// baseline (speedup 1.0000x reference)
#include <cuda_runtime.h>
#include <cuda_fp16.h>
#include <cstdint>

// ---------------------------------------------------------------------------
// GAT: N=4096, F_IN=512, HID=64, H=8, alpha=0.2
//  out[n, h*64+d] = elu( softmax_j(leakyrelu(s[h,n]+d[h,j]), mask=adj) @ Wh )
// exp(leakyrelu(s+d)) factorizes -> no per-edge exp.
// GEMM: fp16 1-term mma.sync.m16n8k16, BK=64, cp.async double-buffered;
// s/d logits fused into GEMM epilogue; Wh stored fp16.
// Attention: FUSED adj-scan + gather, one warp per node, no block barriers,
// no CSR round trip (stream overlap measured ineffective in R13->R14).
// ---------------------------------------------------------------------------

#define N_NODES 4096
#define F_IN    512
#define HID     64
#define NHEADS  8
#define NCOLS   512
#define CAP     192

__device__ __half  g_Whh[N_NODES * NCOLS];     // Wh fp16 [N][H*64]
__device__ float4  g_SAB[N_NODES * NHEADS];    // [i*8+h] = (s, e^s, e^.2s, 0)
__device__ float4  g_DJE[N_NODES * NHEADS];
__device__ __half  g_xh[N_NODES * F_IN];       // x fp16
__device__ __half  g_Wth[NHEADS * HID * F_IN]; // W^T fp16: [h][n][k]

// ---------------------------------------------------------------------------
// Kernel 0: merged prep. Blocks [0,1024): x -> fp16.  [1024,1280): W^T -> fp16.
// ---------------------------------------------------------------------------
__global__ __launch_bounds__(256) void prep_all(const float* __restrict__ x,
                                                const float* __restrict__ W)
{
    if (blockIdx.x < 1024) {
        size_t base = ((size_t)blockIdx.x * 256 + threadIdx.x) * 8;
        float4 p = *(const float4*)(x + base);
        float4 q = *(const float4*)(x + base + 4);
        __align__(16) __half hs[8];
        hs[0] = __float2half_rn(p.x); hs[1] = __float2half_rn(p.y);
        hs[2] = __float2half_rn(p.z); hs[3] = __float2half_rn(p.w);
        hs[4] = __float2half_rn(q.x); hs[5] = __float2half_rn(q.y);
        hs[6] = __float2half_rn(q.z); hs[7] = __float2half_rn(q.w);
        *(uint4*)(g_xh + base) = *(uint4*)hs;
    } else {
        int b  = (blockIdx.x - 1024) * 256 + threadIdx.x;  // 0..65535
        int k4 = (b & 127) * 4;
        int n  = (b >> 7) & 63;
        int h  = b >> 13;
        const float* src = W + (size_t)h * 32768 + (size_t)k4 * 64 + n;
        __align__(8) __half hs[4];
        hs[0] = __float2half_rn(src[0]);
        hs[1] = __float2half_rn(src[64]);
        hs[2] = __float2half_rn(src[128]);
        hs[3] = __float2half_rn(src[192]);
        *(uint2*)(g_Wth + (size_t)h * 32768 + (size_t)n * 512 + k4) = *(uint2*)hs;
    }
}

// ---------------------------------------------------------------------------
// Kernel 1: fp16 1-term GEMM + fused s/d epilogue (unchanged from R15).
// Block: M=128 x N=64 (one head), BK=64, 256 threads, grid 256.
// ---------------------------------------------------------------------------
#define NKB   8
#define KBSZ  64
#define LDH   72
#define A_H   (128 * LDH)
#define B_H   (64 * LDH)
#define BUF_H (A_H + B_H)
#define DYN_BYTES (2 * BUF_H * 2 + 512 + 2048)

__device__ __forceinline__ uint32_t smem_u32(const void* p) {
    uint32_t a;
    asm("{ .reg .u64 t; cvta.to.shared.u64 t, %1; cvt.u32.u64 %0, t; }"
        : "=r"(a) : "l"(p));
    return a;
}
__device__ __forceinline__ void cp16(uint32_t dst, const void* src) {
    asm volatile("cp.async.ca.shared.global [%0], [%1], 16;"
                 :: "r"(dst), "l"(src) : "memory");
}
__device__ __forceinline__ void mma_f16(float* d, uint32_t a0, uint32_t a1,
                                        uint32_t a2, uint32_t a3,
                                        uint32_t b0, uint32_t b1)
{
    asm volatile(
        "mma.sync.aligned.m16n8k16.row.col.f32.f16.f16.f32 "
        "{%0,%1,%2,%3}, {%4,%5,%6,%7}, {%8,%9}, {%0,%1,%2,%3};"
        : "+f"(d[0]), "+f"(d[1]), "+f"(d[2]), "+f"(d[3])
        : "r"(a0), "r"(a1), "r"(a2), "r"(a3), "r"(b0), "r"(b1));
}

__global__ __launch_bounds__(256) void gemm_f16(const float* __restrict__ a_g)
{
    extern __shared__ __align__(16) char sm[];
    __half* tiles = (__half*)sm;
    float*  a_sm  = (float*)(sm + 2 * BUF_H * 2);
    float*  sd_sm = (float*)(sm + 2 * BUF_H * 2 + 512);

    const int tid  = threadIdx.x;
    const int lane = tid & 31, warp = tid >> 5;
    const int h    = blockIdx.x;
    const int m0   = blockIdx.y * 128;
    const int wm   = warp >> 1, wn = warp & 1;
    const int gid  = lane >> 2, tig = lane & 3;

    const __half* xh  = g_xh + (size_t)m0 * F_IN;
    const __half* wth = g_Wth + (size_t)h * 32768;

    if (tid < 128) a_sm[tid] = a_g[h * 128 + tid];

    const uint32_t tiles_u = smem_u32(tiles);

    auto stage = [&](int buf, int k0) {
        uint32_t bu = tiles_u + buf * (BUF_H * 2);
#pragma unroll
        for (int p = 0; p < 6; p++) {
            int id = tid + p * 256;
            if (id < 1024) {
                int r = id >> 3, seg = id & 7;
                cp16(bu + (r * LDH + seg * 8) * 2, xh + (size_t)r * F_IN + k0 + seg * 8);
            } else {
                int q = id - 1024, r = q >> 3, seg = q & 7;
                cp16(bu + (A_H + r * LDH + seg * 8) * 2, wth + (size_t)r * F_IN + k0 + seg * 8);
            }
        }
        asm volatile("cp.async.commit_group;" ::: "memory");
    };

    float acc[2][4][4];
#pragma unroll
    for (int mt = 0; mt < 2; mt++)
#pragma unroll
        for (int nt = 0; nt < 4; nt++)
#pragma unroll
            for (int r = 0; r < 4; r++) acc[mt][nt][r] = 0.f;

    stage(0, 0);

    for (int kb = 0; kb < NKB; kb++) {
        asm volatile("cp.async.wait_group 0;" ::: "memory");
        __syncthreads();
        if (kb + 1 < NKB) stage((kb + 1) & 1, (kb + 1) * KBSZ);

        const __half* Ah = tiles + (kb & 1) * BUF_H;
        const __half* Bh = Ah + A_H;

#pragma unroll
        for (int c = 0; c < 4; c++) {
            const int kb16 = c * 16 + 2 * tig;
            uint32_t bfr[4][2];
#pragma unroll
            for (int nt = 0; nt < 4; nt++) {
                const int col = wn * 32 + nt * 8 + gid;
                bfr[nt][0] = *(const uint32_t*)(Bh + col * LDH + kb16);
                bfr[nt][1] = *(const uint32_t*)(Bh + col * LDH + kb16 + 8);
            }
#pragma unroll
            for (int mt = 0; mt < 2; mt++) {
                const int r0 = wm * 32 + mt * 16 + gid;
                uint32_t ah0 = *(const uint32_t*)(Ah + r0 * LDH + kb16);
                uint32_t ah1 = *(const uint32_t*)(Ah + (r0 + 8) * LDH + kb16);
                uint32_t ah2 = *(const uint32_t*)(Ah + r0 * LDH + kb16 + 8);
                uint32_t ah3 = *(const uint32_t*)(Ah + (r0 + 8) * LDH + kb16 + 8);
#pragma unroll
                for (int nt = 0; nt < 4; nt++)
                    mma_f16(acc[mt][nt], ah0, ah1, ah2, ah3, bfr[nt][0], bfr[nt][1]);
            }
        }
    }

    float sp[2][2], dp[2][2];
#pragma unroll
    for (int mt = 0; mt < 2; mt++) {
        sp[mt][0] = sp[mt][1] = dp[mt][0] = dp[mt][1] = 0.f;
        const int gr = m0 + wm * 32 + mt * 16 + gid;
#pragma unroll
        for (int nt = 0; nt < 4; nt++) {
            const int coll = wn * 32 + nt * 8 + 2 * tig;
            const int col  = h * HID + coll;
            *(__half2*)(g_Whh + (size_t)gr * NCOLS + col) =
                __floats2half2_rn(acc[mt][nt][0], acc[mt][nt][1]);
            *(__half2*)(g_Whh + (size_t)(gr + 8) * NCOLS + col) =
                __floats2half2_rn(acc[mt][nt][2], acc[mt][nt][3]);
#pragma unroll
            for (int cc = 0; cc < 2; cc++) {
                float as = a_sm[coll + cc], ad = a_sm[64 + coll + cc];
                sp[mt][0] = fmaf(acc[mt][nt][cc],     as, sp[mt][0]);
                sp[mt][1] = fmaf(acc[mt][nt][2 + cc], as, sp[mt][1]);
                dp[mt][0] = fmaf(acc[mt][nt][cc],     ad, dp[mt][0]);
                dp[mt][1] = fmaf(acc[mt][nt][2 + cc], ad, dp[mt][1]);
            }
        }
    }
#pragma unroll
    for (int o = 1; o < 4; o <<= 1) {
#pragma unroll
        for (int mt = 0; mt < 2; mt++) {
#pragma unroll
            for (int hf = 0; hf < 2; hf++) {
                sp[mt][hf] += __shfl_xor_sync(0xffffffffu, sp[mt][hf], o);
                dp[mt][hf] += __shfl_xor_sync(0xffffffffu, dp[mt][hf], o);
            }
        }
    }
    if (tig == 0) {
#pragma unroll
        for (int mt = 0; mt < 2; mt++)
#pragma unroll
            for (int hf = 0; hf < 2; hf++) {
                int row = wm * 32 + mt * 16 + gid + hf * 8;
                sd_sm[row * 4 + wn * 2 + 0] = sp[mt][hf];
                sd_sm[row * 4 + wn * 2 + 1] = dp[mt][hf];
            }
    }
    __syncthreads();
    if (tid < 128) {
        float s = sd_sm[tid * 4 + 0] + sd_sm[tid * 4 + 2];
        float d = sd_sm[tid * 4 + 1] + sd_sm[tid * 4 + 3];
        int gr = m0 + tid;
        g_SAB[gr * 8 + h] = make_float4(s, expf(s), expf(0.2f * s), 0.f);
        g_DJE[gr * 8 + h] = make_float4(d, expf(d), expf(0.2f * d), 0.f);
    }
}

// ---------------------------------------------------------------------------
// Kernel 2: FUSED scan + aggregation. One warp per node, 8 nodes/block,
// grid 512. No block barriers. Lane l owns halfs [l*8,l*8+8) (head l>>3)
// and [256+l*8, ...) (head 4+(l>>3)); per-neighbor DJE row read is one
// fully-coalesced 128B line across the warp.
// ---------------------------------------------------------------------------
__global__ __launch_bounds__(256) void attn_fused(const float* __restrict__ adj,
                                                  float* __restrict__ out)
{
    __shared__ int s_list[8][CAP];

    const int tid  = threadIdx.x;
    const int nd   = tid >> 5;          // warp = node slot
    const int lane = tid & 31;
    const int i    = blockIdx.x * 8 + nd;
    const int h0   = lane >> 3;         // 0..3
    const int h1   = h0 + 4;            // 4..7

    // ---- phase 1: scan adj row -> per-lane 128-bit predicate mask ----
    const float4* row4 = (const float4*)(adj + (size_t)i * N_NODES);
    unsigned m[4] = {0u, 0u, 0u, 0u};
#pragma unroll
    for (int it = 0; it < 32; it++) {
        float4 v = row4[it * 32 + lane];            // col = it*128 + lane*4
        unsigned bb = (v.x > 0.f ? 1u : 0u) | (v.y > 0.f ? 2u : 0u) |
                      (v.z > 0.f ? 4u : 0u) | (v.w > 0.f ? 8u : 0u);
        m[it >> 3] |= bb << ((it & 7) * 4);
    }
    int cnt = __popc(m[0]) + __popc(m[1]) + __popc(m[2]) + __popc(m[3]);
    int incl = cnt;
#pragma unroll
    for (int o = 1; o < 32; o <<= 1) {
        int t = __shfl_up_sync(0xffffffffu, incl, o);
        if (lane >= o) incl += t;
    }
    int nn = __shfl_sync(0xffffffffu, incl, 31);
    int p  = incl - cnt;                // exclusive offset (lane-major order)

#pragma unroll
    for (int w = 0; w < 4; w++) {
        unsigned bits = m[w];
        while (bits) {
            int b = __ffs(bits) - 1;
            bits &= bits - 1;
            int it  = w * 8 + (b >> 2);
            int col = it * 128 + lane * 4 + (b & 3);
            if (p < CAP) s_list[nd][p] = col;
            p++;
        }
    }
    nn = min(nn, CAP);
    __syncwarp();

    // ---- phase 2: weighted gather ----
    float4 sab0 = g_SAB[i * 8 + h0];
    float4 sab1 = g_SAB[i * 8 + h1];

    float acc[16];
#pragma unroll
    for (int r = 0; r < 16; r++) acc[r] = 0.f;
    float den0 = 0.f, den1 = 0.f;

    const int* lp = s_list[nd];

#pragma unroll 4
    for (int q = 0; q < nn; q++) {
        int j = lp[q];
        float4 d0 = __ldg(&g_DJE[j * 8 + h0]);
        float4 d1 = __ldg(&g_DJE[j * 8 + h1]);
        float w0 = (sab0.x + d0.x > 0.f) ? sab0.y * d0.y : sab0.z * d0.z;
        float w1 = (sab1.x + d1.x > 0.f) ? sab1.y * d1.y : sab1.z * d1.z;
        const uint4* base = (const uint4*)(g_Whh + ((size_t)j << 9));
        uint4 va = __ldg(base + lane);          // halfs lane*8       (head h0)
        uint4 vb = __ldg(base + 32 + lane);     // halfs 256+lane*8   (head h1)
        float2 a0 = __half22float2(*(__half2*)&va.x);
        float2 a1 = __half22float2(*(__half2*)&va.y);
        float2 a2 = __half22float2(*(__half2*)&va.z);
        float2 a3 = __half22float2(*(__half2*)&va.w);
        float2 b0 = __half22float2(*(__half2*)&vb.x);
        float2 b1 = __half22float2(*(__half2*)&vb.y);
        float2 b2 = __half22float2(*(__half2*)&vb.z);
        float2 b3 = __half22float2(*(__half2*)&vb.w);
        acc[0]  = fmaf(w0, a0.x, acc[0]);  acc[1]  = fmaf(w0, a0.y, acc[1]);
        acc[2]  = fmaf(w0, a1.x, acc[2]);  acc[3]  = fmaf(w0, a1.y, acc[3]);
        acc[4]  = fmaf(w0, a2.x, acc[4]);  acc[5]  = fmaf(w0, a2.y, acc[5]);
        acc[6]  = fmaf(w0, a3.x, acc[6]);  acc[7]  = fmaf(w0, a3.y, acc[7]);
        acc[8]  = fmaf(w1, b0.x, acc[8]);  acc[9]  = fmaf(w1, b0.y, acc[9]);
        acc[10] = fmaf(w1, b1.x, acc[10]); acc[11] = fmaf(w1, b1.y, acc[11]);
        acc[12] = fmaf(w1, b2.x, acc[12]); acc[13] = fmaf(w1, b2.y, acc[13]);
        acc[14] = fmaf(w1, b3.x, acc[14]); acc[15] = fmaf(w1, b3.y, acc[15]);
        den0 += w0;
        den1 += w1;
    }

    float i0 = 1.f / den0, i1 = 1.f / den1;
    float r[16];
#pragma unroll
    for (int c = 0; c < 8; c++) {
        float t = acc[c] * i0;
        r[c] = (t > 0.f) ? t : (expf(t) - 1.f);
    }
#pragma unroll
    for (int c = 8; c < 16; c++) {
        float t = acc[c] * i1;
        r[c] = (t > 0.f) ? t : (expf(t) - 1.f);
    }
    float* dst0 = out + (size_t)i * NCOLS + lane * 8;
    float* dst1 = dst0 + 256;
    *(float4*)(dst0)     = make_float4(r[0],  r[1],  r[2],  r[3]);
    *(float4*)(dst0 + 4) = make_float4(r[4],  r[5],  r[6],  r[7]);
    *(float4*)(dst1)     = make_float4(r[8],  r[9],  r[10], r[11]);
    *(float4*)(dst1 + 4) = make_float4(r[12], r[13], r[14], r[15]);
}

// ---------------------------------------------------------------------------
extern "C" void kernel_launch(void* const* d_in, const int* in_sizes, int n_in,
                              void* d_out, int out_size)
{
    const float* x   = (const float*)d_in[0];   // [4096, 512]
    const float* adj = (const float*)d_in[1];   // [4096, 4096]
    const float* W   = (const float*)d_in[2];   // [8, 512, 64]
    const float* a   = (const float*)d_in[3];   // [8, 128]
    float* out = (float*)d_out;                 // [4096, 512]

    static bool attr_set = false;
    if (!attr_set) {
        cudaFuncSetAttribute(gemm_f16, cudaFuncAttributeMaxDynamicSharedMemorySize, DYN_BYTES);
        attr_set = true;
    }

    prep_all<<<1280, 256>>>(x, W);
    gemm_f16<<<dim3(NHEADS, N_NODES / 128), 256, DYN_BYTES>>>(a);
    attn_fused<<<N_NODES / 8, 256>>>(adj, out);
}